// round 1
// baseline (speedup 1.0000x reference)
#include <cuda_runtime.h>

// Problem constants
#define BATCH 32
#define MN    1024
#define DF    128     // feature dim (D_IN == D_OUT == 128)
#define ED    64      // embedding dim
#define NROWS (BATCH*MN)   // 32768

// Scratch (device globals: no allocation allowed)
__device__ float g_dinv[NROWS];
__device__ float g_z[NROWS*DF];   // dinv-prescaled features (Z)
__device__ float g_y[NROWS*DF];   // layer-1 output

typedef unsigned long long u64;

// ---- packed f32x2 helpers (FFMA2 path: full-rate fp32 on sm_103a) ----
__device__ __forceinline__ u64 pack2(float x, float y) {
    u64 r; asm("mov.b64 %0,{%1,%2};" : "=l"(r) : "f"(x), "f"(y)); return r;
}
__device__ __forceinline__ u64 dup2(float x) {
    u64 r; asm("mov.b64 %0,{%1,%1};" : "=l"(r) : "f"(x)); return r;
}
__device__ __forceinline__ void fma2(u64 &d, u64 a, u64 b) {
    asm("fma.rn.f32x2 %0,%1,%2,%0;" : "+l"(d) : "l"(a), "l"(b));
}
__device__ __forceinline__ float2 unpk(u64 v) {
    float lo, hi; asm("mov.b64 {%0,%1},%2;" : "=f"(lo), "=f"(hi) : "l"(v));
    return make_float2(lo, hi);
}

// ============================================================================
// Kernel 1: degrees.  d[m] = 1 + sum_n relu(E_m . E_n);  g_dinv = d^-1/2
// grid (16 m-tiles, 32 batches), 256 threads, m-tile = 64.
// ============================================================================
__global__ void __launch_bounds__(256) k_degree(const float* __restrict__ E)
{
    __shared__ float EmT[ED * 68];   // [k][m], pitch 68 (16B-aligned rows, no conflicts)
    __shared__ float EnT[ED * 68];
    __shared__ float red[64][17];

    const int tid = threadIdx.x;
    const int tx = tid & 15, ty = tid >> 4;
    const int b = blockIdx.y, mt = blockIdx.x;
    const int mbase = b * MN + mt * 64;
    const int nbase0 = b * MN;

    for (int i = tid; i < 64 * ED; i += 256) {
        int m = i >> 6, k = i & 63;
        EmT[k * 68 + m] = E[(mbase + m) * ED + k];
    }

    float rs[4] = {0.f, 0.f, 0.f, 0.f};

    for (int nt = 0; nt < 16; nt++) {
        __syncthreads();
        for (int i = tid; i < 64 * ED; i += 256) {
            int n = i >> 6, k = i & 63;
            EnT[k * 68 + n] = E[(nbase0 + nt * 64 + n) * ED + k];
        }
        __syncthreads();

        u64 s2[4][2];
        #pragma unroll
        for (int i = 0; i < 4; i++) { s2[i][0] = 0ull; s2[i][1] = 0ull; }

        #pragma unroll 8
        for (int k = 0; k < ED; k++) {
            const float4 a4 = *(const float4*)&EmT[k * 68 + ty * 4];
            const float4 b4 = *(const float4*)&EnT[k * 68 + tx * 4];
            const u64 b01 = pack2(b4.x, b4.y), b23 = pack2(b4.z, b4.w);
            const float am[4] = {a4.x, a4.y, a4.z, a4.w};
            #pragma unroll
            for (int i = 0; i < 4; i++) {
                u64 ad = dup2(am[i]);
                fma2(s2[i][0], ad, b01);
                fma2(s2[i][1], ad, b23);
            }
        }
        #pragma unroll
        for (int i = 0; i < 4; i++) {
            float2 p = unpk(s2[i][0]); rs[i] += fmaxf(p.x, 0.f) + fmaxf(p.y, 0.f);
            float2 q = unpk(s2[i][1]); rs[i] += fmaxf(q.x, 0.f) + fmaxf(q.y, 0.f);
        }
    }

    #pragma unroll
    for (int i = 0; i < 4; i++) red[ty * 4 + i][tx] = rs[i];
    __syncthreads();
    if (tid < 64) {
        float s = 1.0f;   // +1 from the identity in A = adj + I
        #pragma unroll
        for (int j = 0; j < 16; j++) s += red[tid][j];
        g_dinv[mbase + tid] = rsqrtf(s);
    }
}

// ============================================================================
// Kernel 2: Z = dinv ⊙ (In @ W^T).   In: [32768,128], W: [128,128] row-major.
// grid 512 (64-row tiles), 256 threads, dynamic smem.
// ============================================================================
#define GEMM_SMEM ((128*68 + 128*132) * 4)   // XT + WT = 102400 B

__global__ void __launch_bounds__(256) k_gemmw(const float* __restrict__ xext,
                                               const float* __restrict__ W,
                                               int use_internal)
{
    extern __shared__ float sm[];
    float* XT = sm;             // [k 128][m 64]  pitch 68
    float* WT = sm + 128 * 68;  // [k 128][d 128] pitch 132

    const float* __restrict__ in = use_internal ? g_y : xext;

    const int tid = threadIdx.x;
    const int tx = tid & 15, ty = tid >> 4;
    const int rbase = blockIdx.x * 64;

    for (int i = tid; i < 64 * 128; i += 256) {
        int m = i >> 7, k = i & 127;
        XT[k * 68 + m] = in[(rbase + m) * 128 + k];
    }
    for (int i = tid; i < 128 * 128; i += 256) {
        int d = i >> 7, k = i & 127;
        WT[k * 132 + d] = W[i];
    }
    __syncthreads();

    u64 acc[4][4];
    #pragma unroll
    for (int i = 0; i < 4; i++)
        #pragma unroll
        for (int j = 0; j < 4; j++) acc[i][j] = 0ull;

    #pragma unroll 8
    for (int k = 0; k < 128; k++) {
        const float4 a4 = *(const float4*)&XT[k * 68 + ty * 4];
        const float4 w0 = *(const float4*)&WT[k * 132 + tx * 8];
        const float4 w1 = *(const float4*)&WT[k * 132 + tx * 8 + 4];
        const u64 wp[4] = {pack2(w0.x, w0.y), pack2(w0.z, w0.w),
                           pack2(w1.x, w1.y), pack2(w1.z, w1.w)};
        const float am[4] = {a4.x, a4.y, a4.z, a4.w};
        #pragma unroll
        for (int i = 0; i < 4; i++) {
            u64 ad = dup2(am[i]);
            #pragma unroll
            for (int j = 0; j < 4; j++) fma2(acc[i][j], ad, wp[j]);
        }
    }

    #pragma unroll
    for (int i = 0; i < 4; i++) {
        const int row = rbase + ty * 4 + i;
        const float sc = g_dinv[row];
        float2 p0 = unpk(acc[i][0]), p1 = unpk(acc[i][1]);
        float2 p2 = unpk(acc[i][2]), p3 = unpk(acc[i][3]);
        float4 o0 = make_float4(sc * p0.x, sc * p0.y, sc * p1.x, sc * p1.y);
        float4 o1 = make_float4(sc * p2.x, sc * p2.y, sc * p3.x, sc * p3.y);
        *(float4*)&g_z[row * 128 + tx * 8]     = o0;
        *(float4*)&g_z[row * 128 + tx * 8 + 4] = o1;
    }
}

// ============================================================================
// Kernel 3: propagation.  out = relu( dinv_m ⊙ ( S @ Z + Z ) ),
//   S[m][n] = relu(E_m . E_n) recomputed from E tiles (identity via +Z[m]).
// grid (16 m-tiles, 32 batches), 256 threads, dynamic smem (EnT/Zs share U).
// ============================================================================
#define PROP_SMEM ((64*68 + 64*68 + 64*128) * 4)   // EmT + ST + U = 67584 B

__global__ void __launch_bounds__(256) k_prop(const float* __restrict__ E,
                                              float* __restrict__ outext,
                                              int to_internal)
{
    extern __shared__ float sm[];
    float* EmT = sm;               // [k 64][m 64] pitch 68
    float* ST  = sm + 64 * 68;     // [n 64][m 64] pitch 68
    float* U   = sm + 2 * 64 * 68; // stage1: EnT [k][n] p68; stage2: Zs [n][d] p128

    float* __restrict__ out = to_internal ? g_y : outext;

    const int tid = threadIdx.x;
    const int tx = tid & 15, ty = tid >> 4;
    const int b = blockIdx.y, mt = blockIdx.x;
    const int mbase = b * MN + mt * 64;
    const int nbase0 = b * MN;

    for (int i = tid; i < 64 * ED; i += 256) {
        int m = i >> 6, k = i & 63;
        EmT[k * 68 + m] = E[(mbase + m) * ED + k];
    }

    u64 acc[4][4];
    #pragma unroll
    for (int i = 0; i < 4; i++)
        #pragma unroll
        for (int j = 0; j < 4; j++) acc[i][j] = 0ull;

    for (int nt = 0; nt < 16; nt++) {
        const int nb = nbase0 + nt * 64;
        __syncthreads();   // previous stage-2 finished with U / ST
        for (int i = tid; i < 64 * ED; i += 256) {
            int n = i >> 6, k = i & 63;
            U[k * 68 + n] = E[(nb + n) * ED + k];
        }
        __syncthreads();

        // --- stage 1: S tile = relu(Em . En) ---
        u64 s2[4][2];
        #pragma unroll
        for (int i = 0; i < 4; i++) { s2[i][0] = 0ull; s2[i][1] = 0ull; }

        #pragma unroll 8
        for (int k = 0; k < ED; k++) {
            const float4 a4 = *(const float4*)&EmT[k * 68 + ty * 4];
            const float4 b4 = *(const float4*)&U[k * 68 + tx * 4];
            const u64 b01 = pack2(b4.x, b4.y), b23 = pack2(b4.z, b4.w);
            const float am[4] = {a4.x, a4.y, a4.z, a4.w};
            #pragma unroll
            for (int i = 0; i < 4; i++) {
                u64 ad = dup2(am[i]);
                fma2(s2[i][0], ad, b01);
                fma2(s2[i][1], ad, b23);
            }
        }
        float sv[4][4];
        #pragma unroll
        for (int i = 0; i < 4; i++) {
            float2 p = unpk(s2[i][0]); sv[i][0] = fmaxf(p.x, 0.f); sv[i][1] = fmaxf(p.y, 0.f);
            float2 q = unpk(s2[i][1]); sv[i][2] = fmaxf(q.x, 0.f); sv[i][3] = fmaxf(q.y, 0.f);
        }
        #pragma unroll
        for (int j = 0; j < 4; j++) {
            *(float4*)&ST[(tx * 4 + j) * 68 + ty * 4] =
                make_float4(sv[0][j], sv[1][j], sv[2][j], sv[3][j]);
        }
        __syncthreads();   // ST ready; U free for Zs

        for (int i = tid; i < 64 * 128; i += 256) {
            int n = i >> 7, d = i & 127;
            U[n * 128 + d] = g_z[(nb + n) * 128 + d];
        }
        __syncthreads();

        // --- stage 2: acc += S @ Z ---
        #pragma unroll 4
        for (int n = 0; n < 64; n++) {
            const float4 s4 = *(const float4*)&ST[n * 68 + ty * 4];
            const float4 z0 = *(const float4*)&U[n * 128 + tx * 8];
            const float4 z1 = *(const float4*)&U[n * 128 + tx * 8 + 4];
            const u64 zp[4] = {pack2(z0.x, z0.y), pack2(z0.z, z0.w),
                               pack2(z1.x, z1.y), pack2(z1.z, z1.w)};
            const float ss[4] = {s4.x, s4.y, s4.z, s4.w};
            #pragma unroll
            for (int i = 0; i < 4; i++) {
                u64 ad = dup2(ss[i]);
                #pragma unroll
                for (int j = 0; j < 4; j++) fma2(acc[i][j], ad, zp[j]);
            }
        }
    }

    // epilogue: out = relu(dinv_m * (acc + Z[m]))  (identity term = +Z[m])
    #pragma unroll
    for (int i = 0; i < 4; i++) {
        const int row = mbase + ty * 4 + i;
        const float sc = g_dinv[row];
        const float4 zr0 = *(const float4*)&g_z[row * 128 + tx * 8];
        const float4 zr1 = *(const float4*)&g_z[row * 128 + tx * 8 + 4];
        float2 p0 = unpk(acc[i][0]), p1 = unpk(acc[i][1]);
        float2 p2 = unpk(acc[i][2]), p3 = unpk(acc[i][3]);
        float4 o0 = make_float4(fmaxf(sc * (p0.x + zr0.x), 0.f),
                                fmaxf(sc * (p0.y + zr0.y), 0.f),
                                fmaxf(sc * (p1.x + zr0.z), 0.f),
                                fmaxf(sc * (p1.y + zr0.w), 0.f));
        float4 o1 = make_float4(fmaxf(sc * (p2.x + zr1.x), 0.f),
                                fmaxf(sc * (p2.y + zr1.y), 0.f),
                                fmaxf(sc * (p3.x + zr1.z), 0.f),
                                fmaxf(sc * (p3.y + zr1.w), 0.f));
        *(float4*)&out[row * 128 + tx * 8]     = o0;
        *(float4*)&out[row * 128 + tx * 8 + 4] = o1;
    }
}

// ============================================================================
extern "C" void kernel_launch(void* const* d_in, const int* in_sizes, int n_in,
                              void* d_out, int out_size)
{
    (void)in_sizes; (void)n_in; (void)out_size;
    const float* X  = (const float*)d_in[0];   // node_feature_group [32768,128]
    const float* E  = (const float*)d_in[1];   // embedding_group    [32768,64]
    const float* W1 = (const float*)d_in[2];   // [128,128]
    const float* W2 = (const float*)d_in[3];   // [128,128]
    float* out = (float*)d_out;

    cudaFuncSetAttribute(k_gemmw, cudaFuncAttributeMaxDynamicSharedMemorySize, GEMM_SMEM);
    cudaFuncSetAttribute(k_prop,  cudaFuncAttributeMaxDynamicSharedMemorySize, PROP_SMEM);

    k_degree<<<dim3(16, 32), 256>>>(E);
    k_gemmw<<<512, 256, GEMM_SMEM>>>(X, W1, 0);        // g_z = dinv ⊙ (X @ W1^T)
    k_prop<<<dim3(16, 32), 256, PROP_SMEM>>>(E, nullptr, 1);   // g_y = layer-1 out
    k_gemmw<<<512, 256, GEMM_SMEM>>>(nullptr, W2, 1);  // g_z = dinv ⊙ (Y1 @ W2^T)
    k_prop<<<dim3(16, 32), 256, PROP_SMEM>>>(E, out, 0);       // final output
}

// round 4
// speedup vs baseline: 2.9898x; 2.9898x over previous
#include <cuda_runtime.h>
#include <cstdint>

#define BATCH 32
#define MN    1024
#define DF    128
#define ED    64
#define NROWS (BATCH*MN)   // 32768

// ---------------- device scratch (no runtime allocation allowed) ----------------
__device__ float g_S   [(size_t)BATCH*MN*MN];   // 128 MB: S = relu(E E^T) per graph
__device__ float g_degp[NROWS*32];              // row-sum partials (nt*4 + wx)
__device__ float g_dinv[NROWS];
__device__ float g_z   [(size_t)NROWS*DF];      // Z = dinv ⊙ (In @ W^T), row-major
__device__ float g_y   [(size_t)NROWS*DF];      // layer-1 output

// ---------------- helpers ----------------
__device__ __forceinline__ uint32_t smem_u32(const void* p){
    uint32_t a;
    asm("{ .reg .u64 t; cvta.to.shared.u64 t, %1; cvt.u32.u64 %0, t; }" : "=r"(a) : "l"(p));
    return a;
}
__device__ __forceinline__ void cpa16(uint32_t d, const void* s){
    asm volatile("cp.async.cg.shared.global [%0], [%1], 16;" :: "r"(d), "l"(s));
}
#define CP_COMMIT() asm volatile("cp.async.commit_group;" ::: "memory")
#define CP_WAIT0()  asm volatile("cp.async.wait_group 0;" ::: "memory")
#define CP_WAIT1()  asm volatile("cp.async.wait_group 1;" ::: "memory")

// Dekker-style tf32 split: hi exactly representable in tf32 (low 13 bits zeroed),
// lo = v - hi exact in fp32; HMMA reads only the top 19 bits of each operand.
__device__ __forceinline__ void split(float v, uint32_t& h, uint32_t& l){
    uint32_t u = __float_as_uint(v) & 0xFFFFE000u;
    h = u;
    l = __float_as_uint(v - __uint_as_float(u));
}

__device__ __forceinline__ void mma8(float c[4], const uint32_t a[4], const uint32_t b[2]){
    asm volatile(
        "mma.sync.aligned.m16n8k8.row.col.f32.tf32.tf32.f32 "
        "{%0,%1,%2,%3}, {%4,%5,%6,%7}, {%8,%9}, {%0,%1,%2,%3};"
        : "+f"(c[0]), "+f"(c[1]), "+f"(c[2]), "+f"(c[3])
        : "r"(a[0]), "r"(a[1]), "r"(a[2]), "r"(a[3]), "r"(b[0]), "r"(b[1]));
}

// One k8 step for a 128x128 CTA tile, 8 warps of 64x32 (wy in {0,1}, wx in {0..3}).
// A smem: [m][k] pitch PA.  B smem: BKN ? [k][n] pitch PB : [n][k] pitch PB.
// 3-product tf32 split: c += ah*bh + al*bh + ah*bl   (al*bl ~ 2^-26, dropped)
template<int PA, int PB, bool BKN>
__device__ __forceinline__ void mma_step(const float* __restrict__ As,
                                         const float* __restrict__ Bs,
                                         int kk, int wy, int wx, int lane,
                                         float c[4][4][4])
{
    const int g = lane >> 2, t = lane & 3;
    uint32_t ah[4][4], al[4][4];
    #pragma unroll
    for (int i = 0; i < 4; i++){
        const float* ap = As + (wy*64 + i*16 + g)*PA + kk + t;
        split(ap[0],        ah[i][0], al[i][0]);
        split(ap[8*PA],     ah[i][1], al[i][1]);
        split(ap[4],        ah[i][2], al[i][2]);
        split(ap[8*PA + 4], ah[i][3], al[i][3]);
    }
    #pragma unroll
    for (int j = 0; j < 4; j++){
        const int n0 = wx*32 + j*8 + g;
        const float* bp = BKN ? (Bs + (size_t)(kk + t)*PB + n0)
                              : (Bs + (size_t)n0*PB + kk + t);
        uint32_t bh[2], bl[2];
        split(bp[0], bh[0], bl[0]);
        split(BKN ? bp[4*PB] : bp[4], bh[1], bl[1]);
        #pragma unroll
        for (int i = 0; i < 4; i++){
            mma8(c[i][j], ah[i], bh);
            mma8(c[i][j], al[i], bh);
            mma8(c[i][j], ah[i], bl);
        }
    }
}

// ============================================================================
// Kernel 1: S-build.  S tile = relu(Em En^T), K=64; + row-sum partials.
// grid (8 mt, 8 nt, 32 g), 256 threads.
// ============================================================================
#define SB_PITCH 68
#define SB_TILE  (128*SB_PITCH)          // floats
#define SB_SMEM  (2*SB_TILE*4)           // 69632 B

__global__ void __launch_bounds__(256,2) k_sbuild(const float* __restrict__ E)
{
    extern __shared__ float sm[];
    const uint32_t smb = smem_u32(sm);
    const int tid = threadIdx.x, lane = tid & 31, wid = tid >> 5;
    const int wy = wid >> 2, wx = wid & 3;
    const int mt = blockIdx.x, nt = blockIdx.y, gb = blockIdx.z;

    const float* Emg = E + (size_t)(gb*MN + mt*128)*ED;
    const float* Eng = E + (size_t)(gb*MN + nt*128)*ED;
    // Each tile: 128 rows x 16 float4 = 2048 float4  ->  8 rounds of 256 threads
    #pragma unroll
    for (int r = 0; r < 8; r++){
        int id = r*256 + tid;
        int m = id >> 4, f = id & 15;
        cpa16(smb + m*272 + f*16,               Emg + (size_t)m*ED + f*4);
        cpa16(smb + SB_TILE*4 + m*272 + f*16,   Eng + (size_t)m*ED + f*4);
    }
    CP_COMMIT(); CP_WAIT0();
    __syncthreads();

    float c4[4][4][4] = {};
    #pragma unroll
    for (int kk = 0; kk < 64; kk += 8)
        mma_step<SB_PITCH, SB_PITCH, false>(sm, sm + SB_TILE, kk, wy, wx, lane, c4);

    // epilogue: relu, store S tile, warp-reduced row-sum partials
    const int g = lane >> 2, t = lane & 3;
    const int rowbase = gb*MN + mt*128;
    #pragma unroll
    for (int i = 0; i < 4; i++){
        #pragma unroll
        for (int h = 0; h < 2; h++){
            const int row = rowbase + wy*64 + i*16 + g + h*8;
            float* sr = g_S + (size_t)row*MN + nt*128;
            float rsum = 0.f;
            #pragma unroll
            for (int j = 0; j < 4; j++){
                float v0 = fmaxf(c4[i][j][h*2+0], 0.f);
                float v1 = fmaxf(c4[i][j][h*2+1], 0.f);
                rsum += v0 + v1;
                *(float2*)&sr[wx*32 + j*8 + 2*t] = make_float2(v0, v1);
            }
            rsum += __shfl_xor_sync(0xFFFFFFFFu, rsum, 1);
            rsum += __shfl_xor_sync(0xFFFFFFFFu, rsum, 2);
            if (t == 0) g_degp[row*32 + nt*4 + wx] = rsum;
        }
    }
}

// ============================================================================
// Kernel 2: dinv = rsqrt(1 + sum of 32 partials)
// ============================================================================
__global__ void k_dinv()
{
    const int i = blockIdx.x*256 + threadIdx.x;
    float s = 1.0f;                      // +I in A = adj + I
    #pragma unroll
    for (int j = 0; j < 32; j++) s += g_degp[i*32 + j];
    g_dinv[i] = rsqrtf(s);
}

// ============================================================================
// Kernel 3: Z = dinv ⊙ (In @ W^T).  K=128, 4 chunks of 32, double-buffered.
// grid 256 (128-row tiles), 256 threads.
// ============================================================================
#define GW_PITCH 36
#define GW_TILE  (128*GW_PITCH)          // 4608 floats
#define GW_STAGE (2*GW_TILE)             // A + B
#define GW_SMEM  (2*GW_STAGE*4)          // 73728 B

__global__ void __launch_bounds__(256,2) k_gemmw(const float* __restrict__ xin,
                                                 const float* __restrict__ W,
                                                 int use_internal)
{
    extern __shared__ float sm[];
    const uint32_t smb = smem_u32(sm);
    const float* __restrict__ in = use_internal ? g_y : xin;
    const int tid = threadIdx.x, lane = tid & 31, wid = tid >> 5;
    const int wy = wid >> 2, wx = wid & 3;
    const int rbase = blockIdx.x*128;

    auto copy = [&](int c){
        const uint32_t ab = smb + (uint32_t)(c & 1)*GW_STAGE*4;
        const uint32_t bb = ab + GW_TILE*4;
        #pragma unroll
        for (int r = 0; r < 4; r++){
            int id = r*256 + tid;        // 1024 float4: 128 rows x 8
            int m = id >> 3, f = id & 7;
            cpa16(ab + m*144 + f*16, in + (size_t)(rbase + m)*128 + c*32 + f*4);
            cpa16(bb + m*144 + f*16, W  + (size_t)m*128          + c*32 + f*4);
        }
        CP_COMMIT();
    };

    float c4[4][4][4] = {};
    copy(0);
    for (int c = 0; c < 4; c++){
        if (c < 3){ copy(c + 1); CP_WAIT1(); } else { CP_WAIT0(); }
        __syncthreads();
        const float* As = sm + (c & 1)*GW_STAGE;
        const float* Bs = As + GW_TILE;
        #pragma unroll
        for (int kk = 0; kk < 32; kk += 8)
            mma_step<GW_PITCH, GW_PITCH, false>(As, Bs, kk, wy, wx, lane, c4);
        __syncthreads();
    }

    const int g = lane >> 2, t = lane & 3;
    #pragma unroll
    for (int i = 0; i < 4; i++){
        #pragma unroll
        for (int h = 0; h < 2; h++){
            const int row = rbase + wy*64 + i*16 + g + h*8;
            const float sc = g_dinv[row];
            float* zr = g_z + (size_t)row*128;
            #pragma unroll
            for (int j = 0; j < 4; j++){
                *(float2*)&zr[wx*32 + j*8 + 2*t] =
                    make_float2(sc*c4[i][j][h*2], sc*c4[i][j][h*2+1]);
            }
        }
    }
}

// ============================================================================
// Kernel 4: propagation.  out = relu(dinv_m ⊙ (S@Z + Z_m)).  K=1024, 32 chunks.
// grid (8 mt, 32 g), 256 threads.
// ============================================================================
#define PA_PITCH 36
#define PB_PITCH 132
#define PR_ATILE (128*PA_PITCH)          // 4608 floats
#define PR_BTILE (32*PB_PITCH)           // 4224 floats
#define PR_STAGE (PR_ATILE + PR_BTILE)   // 8832 floats
#define PR_SMEM  (2*PR_STAGE*4)          // 70656 B

__global__ void __launch_bounds__(256,2) k_prop(float* __restrict__ outext, int to_internal)
{
    extern __shared__ float sm[];
    const uint32_t smb = smem_u32(sm);
    const int tid = threadIdx.x, lane = tid & 31, wid = tid >> 5;
    const int wy = wid >> 2, wx = wid & 3;
    const int mt = blockIdx.x, gb = blockIdx.y;
    float* __restrict__ dst = to_internal ? g_y : outext;

    const float* Sbase = g_S + (size_t)(gb*MN + mt*128)*MN;
    const float* Zbase = g_z + (size_t)gb*MN*128;

    auto copy = [&](int c){
        const uint32_t ab = smb + (uint32_t)(c & 1)*PR_STAGE*4;
        const uint32_t bb = ab + PR_ATILE*4;
        #pragma unroll
        for (int r = 0; r < 4; r++){
            int id = r*256 + tid;
            int m = id >> 3, f = id & 7;      // A: 128 rows x 8 float4
            cpa16(ab + m*144 + f*16, Sbase + (size_t)m*MN + c*32 + f*4);
            int n = id >> 5, fb = id & 31;    // B: 32 rows x 32 float4
            cpa16(bb + n*528 + fb*16, Zbase + (size_t)(c*32 + n)*128 + fb*4);
        }
        CP_COMMIT();
    };

    float c4[4][4][4] = {};
    copy(0);
    for (int c = 0; c < 32; c++){
        if (c < 31){ copy(c + 1); CP_WAIT1(); } else { CP_WAIT0(); }
        __syncthreads();
        const float* As = sm + (c & 1)*PR_STAGE;
        const float* Bs = As + PR_ATILE;
        #pragma unroll
        for (int kk = 0; kk < 32; kk += 8)
            mma_step<PA_PITCH, PB_PITCH, true>(As, Bs, kk, wy, wx, lane, c4);
        __syncthreads();
    }

    const int g = lane >> 2, t = lane & 3;
    const int rowbase = gb*MN + mt*128;
    #pragma unroll
    for (int i = 0; i < 4; i++){
        #pragma unroll
        for (int h = 0; h < 2; h++){
            const int row = rowbase + wy*64 + i*16 + g + h*8;
            const float sc = g_dinv[row];
            const float* zr = g_z + (size_t)row*128;
            float* orow = dst + (size_t)row*128;
            #pragma unroll
            for (int j = 0; j < 4; j++){
                const int col = wx*32 + j*8 + 2*t;
                float2 z = *(const float2*)&zr[col];
                float2 o;
                o.x = fmaxf(sc*(c4[i][j][h*2]   + z.x), 0.f);
                o.y = fmaxf(sc*(c4[i][j][h*2+1] + z.y), 0.f);
                *(float2*)&orow[col] = o;
            }
        }
    }
}

// ============================================================================
extern "C" void kernel_launch(void* const* d_in, const int* in_sizes, int n_in,
                              void* d_out, int out_size)
{
    (void)in_sizes; (void)n_in; (void)out_size;
    const float* X  = (const float*)d_in[0];
    const float* E  = (const float*)d_in[1];
    const float* W1 = (const float*)d_in[2];
    const float* W2 = (const float*)d_in[3];
    float* out = (float*)d_out;

    cudaFuncSetAttribute(k_sbuild, cudaFuncAttributeMaxDynamicSharedMemorySize, SB_SMEM);
    cudaFuncSetAttribute(k_gemmw,  cudaFuncAttributeMaxDynamicSharedMemorySize, GW_SMEM);
    cudaFuncSetAttribute(k_prop,   cudaFuncAttributeMaxDynamicSharedMemorySize, PR_SMEM);

    k_sbuild<<<dim3(8, 8, 32), 256, SB_SMEM>>>(E);
    k_dinv  <<<NROWS/256, 256>>>();
    k_gemmw <<<256, 256, GW_SMEM>>>(X, W1, 0);
    k_prop  <<<dim3(8, 32), 256, PR_SMEM>>>(nullptr, 1);
    k_gemmw <<<256, 256, GW_SMEM>>>(nullptr, W2, 1);
    k_prop  <<<dim3(8, 32), 256, PR_SMEM>>>(out, 0);
}